// round 8
// baseline (speedup 1.0000x reference)
#include <cuda_runtime.h>
#include <math.h>

#define NMAX 100000
#define EMAX 1000000

// ---------------- scratch (static device arrays; no allocation) ----------------
__device__ float4 g_h4[(size_t)NMAX * 32];        // h [N,128] as float4
__device__ float4 g_asrc4[NMAX];                  // a_src [N,4]
__device__ float4 g_adst4[NMAX];                  // a_dst [N,4]
__device__ int    g_cnt[NMAX];                    // in-degree counts
__device__ int    g_rowptr[NMAX + 1];             // CSR row pointers (by dst)
__device__ int    g_cur[NMAX];                    // fill cursors
__device__ int    g_part[256];                    // scan block partials
__device__ int    g_adj[EMAX];                    // adjacency: src ids grouped by dst
__device__ float4 g_ex4[EMAX];                    // per-edge softmax numerators [E,4]
__device__ int    g_is64;                         // edge_index dtype flag

// ---------------- helpers ----------------
__device__ __forceinline__ int load_idx(const void* ei, long long i, int is64) {
    if (is64) return (int)((const long long*)ei)[i];
    return ((const int*)ei)[i];
}
__device__ __forceinline__ float lrelu(float v) { return v >= 0.f ? v : 0.2f * v; }

#define FMA2(a, xx, ww) asm("fma.rn.f32x2 %0, %1, %2, %0;" : "+l"(a) : "l"(xx), "l"(ww))

// ---------------- init: zero counts + dtype detect ----------------
__global__ void k_init(const void* ei, int n) {
    int i = blockIdx.x * blockDim.x + threadIdx.x;
    if (i < n) g_cnt[i] = 0;
    if (i == 0) {
        const long long* p = (const long long*)ei;
        int ok = 1;
        for (int j = 0; j < 8; j++) {
            long long v = p[j];
            if (v < 0 || v >= n) ok = 0;
        }
        g_is64 = ok;
    }
}

// ---------------- shfl SGEMM: h = x @ W, fused attention dots ----------------
// 256 threads, 8 warps; warp handles 8 rows, lane covers cols lane*4..lane*4+3.
// W (64KB) is the ONLY smem stream (conflict-free per-lane LDS.128); x stays in
// registers, broadcast via shfl (MIO pipe, off the smem crossbar).
#define GR 64
__global__ void __launch_bounds__(256) k_gemm(
    const float* __restrict__ x, const float* __restrict__ W,
    const float* __restrict__ att_src, const float* __restrict__ att_dst, int n)
{
    extern __shared__ float sw[];                 // [128][128] f32 (64KB)
    const int tid = threadIdx.x;
    {
        const float4* W4 = (const float4*)W;
        float4* s4 = (float4*)sw;
        for (int i = tid; i < 128 * 32; i += 256) s4[i] = W4[i];
    }
    __syncthreads();

    const int lane = tid & 31;
    const int wid = tid >> 5;
    const int rowbase = blockIdx.x * GR + wid * 8;
    const unsigned FULL = 0xffffffffu;
    const ulonglong2* swp = (const ulonglong2*)sw;   // k*32 + lane -> 4 cols (16B)
    const float4 as4 = ((const float4*)att_src)[lane];
    const float4 ad4 = ((const float4*)att_dst)[lane];

    float xr[8][4];
#pragma unroll
    for (int r = 0; r < 8; r++) {
        int row = min(rowbase + r, n - 1);
        const float* xp = x + (size_t)row * 128;
#pragma unroll
        for (int j = 0; j < 4; j++) xr[r][j] = xp[j * 32 + lane];
    }

    unsigned long long acc[8][2];
#pragma unroll
    for (int r = 0; r < 8; r++) { acc[r][0] = 0ull; acc[r][1] = 0ull; }

    for (int j = 0; j < 4; j++) {
#pragma unroll
        for (int kk = 0; kk < 32; kk++) {
            ulonglong2 wv = swp[(j * 32 + kk) * 32 + lane];
#pragma unroll
            for (int r = 0; r < 8; r++) {
                float xk = __shfl_sync(FULL, xr[r][j], kk);
                unsigned long long xp2;
                asm("mov.b64 %0, {%1, %1};" : "=l"(xp2) : "f"(xk));
                FMA2(acc[r][0], xp2, wv.x);
                FMA2(acc[r][1], xp2, wv.y);
            }
        }
    }

#pragma unroll
    for (int r = 0; r < 8; r++) {
        int row = rowbase + r;
        if (row < n) {
            float4 h4;
            asm("mov.b64 {%0, %1}, %2;" : "=f"(h4.x), "=f"(h4.y) : "l"(acc[r][0]));
            asm("mov.b64 {%0, %1}, %2;" : "=f"(h4.z), "=f"(h4.w) : "l"(acc[r][1]));
            g_h4[(size_t)row * 32 + lane] = h4;
            float ps = h4.x * as4.x + h4.y * as4.y + h4.z * as4.z + h4.w * as4.w;
            float pd = h4.x * ad4.x + h4.y * ad4.y + h4.z * ad4.z + h4.w * ad4.w;
            ps += __shfl_xor_sync(FULL, ps, 4);
            pd += __shfl_xor_sync(FULL, pd, 4);
            ps += __shfl_xor_sync(FULL, ps, 2);
            pd += __shfl_xor_sync(FULL, pd, 2);
            ps += __shfl_xor_sync(FULL, ps, 1);
            pd += __shfl_xor_sync(FULL, pd, 1);
            if ((lane & 7) == 0) {
                ((float*)g_asrc4)[row * 4 + (lane >> 3)] = ps;
                ((float*)g_adst4)[row * 4 + (lane >> 3)] = pd;
            }
        }
    }
}

// ---------------- CSR build: histogram ----------------
__global__ void k_hist(const void* __restrict__ ei, int E) {
    int e = blockIdx.x * blockDim.x + threadIdx.x;
    if (e >= E) return;
    int dst = load_idx(ei, (long long)E + e, g_is64);
    atomicAdd(&g_cnt[dst], 1);
}

// ---------------- CSR build: scan (3 phases) ----------------
#define SCAN_BLK 1024
__global__ void k_scan1(int n) {
    __shared__ int sred[256];
    int b = blockIdx.x, t = threadIdx.x;
    int base = b * SCAN_BLK + t * 4;
    int s = 0;
#pragma unroll
    for (int u = 0; u < 4; u++) { int idx = base + u; if (idx < n) s += g_cnt[idx]; }
    sred[t] = s; __syncthreads();
    for (int off = 128; off > 0; off >>= 1) {
        if (t < off) sred[t] += sred[t + off];
        __syncthreads();
    }
    if (t == 0) g_part[b] = sred[0];
}
__global__ void k_scan2(int nb) {
    __shared__ int sp[128];
    int t = threadIdx.x;
    int v = (t < nb) ? g_part[t] : 0;
    sp[t] = v; __syncthreads();
    for (int off = 1; off < 128; off <<= 1) {
        int u = (t >= off) ? sp[t - off] : 0;
        __syncthreads();
        sp[t] += u;
        __syncthreads();
    }
    if (t < nb) g_part[t] = sp[t] - v;
}
__global__ void k_scan3(int n, int E) {
    __shared__ int ssum[256];
    int b = blockIdx.x, t = threadIdx.x;
    int base = b * SCAN_BLK + t * 4;
    int c[4]; int s = 0;
#pragma unroll
    for (int u = 0; u < 4; u++) { int idx = base + u; c[u] = (idx < n) ? g_cnt[idx] : 0; s += c[u]; }
    ssum[t] = s; __syncthreads();
    for (int off = 1; off < 256; off <<= 1) {
        int u = (t >= off) ? ssum[t - off] : 0;
        __syncthreads();
        ssum[t] += u;
        __syncthreads();
    }
    int run = g_part[b] + ssum[t] - s;
#pragma unroll
    for (int u = 0; u < 4; u++) {
        int idx = base + u;
        if (idx < n) { g_rowptr[idx] = run; g_cur[idx] = run; run += c[u]; }
    }
    if (b == 0 && t == 0) g_rowptr[n] = E;
}

// ---------------- CSR build + edge softmax numerators ----------------
// Computes ex4 = exp(lrelu(a_src[src] + a_dst[dst])) here (1M-thread latency
// hiding) so the gather kernel needs no scattered a_src pass, no smem staging,
// no syncwarp. Logits are tiny (|alpha| < ~10) so no max-shift is needed.
__global__ void k_fill(const void* __restrict__ ei, int E) {
    int e = blockIdx.x * blockDim.x + threadIdx.x;
    if (e >= E) return;
    int is64 = g_is64;
    int src = load_idx(ei, e, is64);
    int dst = load_idx(ei, (long long)E + e, is64);
    int pos = atomicAdd(&g_cur[dst], 1);
    float4 as = g_asrc4[src];
    float4 ad = g_adst4[dst];
    float4 ex;
    ex.x = __expf(lrelu(as.x + ad.x));
    ex.y = __expf(lrelu(as.y + ad.y));
    ex.z = __expf(lrelu(as.z + ad.z));
    ex.w = __expf(lrelu(as.w + ad.w));
    g_adj[pos] = src;
    g_ex4[pos] = ex;
}

// ---------------- fused gather: weighted aggregation + normalize + bias ----------------
// One warp per dst node. Lane l handles output cols 4l..4l+3 (head = l>>3).
// (src, ex4) read via warp-broadcast LDG of sequential addresses (L1-hot).
// Every lane sees every edge weight -> denominator is a free scalar running
// sum; no warp reductions, no shared memory, no syncwarp.
__global__ void __launch_bounds__(256) k_gather(
    const float* __restrict__ bias, float* __restrict__ out, int n)
{
    const int lane = threadIdx.x & 31;
    const int i = (blockIdx.x * blockDim.x + threadIdx.x) >> 5;
    if (i >= n) return;
    const int hidx = lane >> 3;

    int start = g_rowptr[i];
    int deg = g_rowptr[i + 1] - start;

    float4 acc = make_float4(0.f, 0.f, 0.f, 0.f);
    float den = 0.f;

    int j = 0;
    for (; j + 8 <= deg; j += 8) {
        int s[8];
        float w[8];
#pragma unroll
        for (int u = 0; u < 8; u++) {
            s[u] = g_adj[start + j + u];
            float4 e4 = g_ex4[start + j + u];
            w[u] = (hidx == 0) ? e4.x : (hidx == 1) ? e4.y : (hidx == 2) ? e4.z : e4.w;
        }
        float4 hv[8];
#pragma unroll
        for (int u = 0; u < 8; u++) hv[u] = g_h4[(size_t)s[u] * 32 + lane];
#pragma unroll
        for (int u = 0; u < 8; u++) {
            den += w[u];
            acc.x += w[u] * hv[u].x; acc.y += w[u] * hv[u].y;
            acc.z += w[u] * hv[u].z; acc.w += w[u] * hv[u].w;
        }
    }
    for (; j < deg; j++) {
        int sj = g_adj[start + j];
        float4 e4 = g_ex4[start + j];
        float w = (hidx == 0) ? e4.x : (hidx == 1) ? e4.y : (hidx == 2) ? e4.z : e4.w;
        float4 hv = g_h4[(size_t)sj * 32 + lane];
        den += w;
        acc.x += w * hv.x; acc.y += w * hv.y; acc.z += w * hv.z; acc.w += w * hv.w;
    }

    // self-loop contribution
    {
        float4 as = g_asrc4[i];
        float4 ad = g_adst4[i];
        float4 exs;
        exs.x = __expf(lrelu(as.x + ad.x));
        exs.y = __expf(lrelu(as.y + ad.y));
        exs.z = __expf(lrelu(as.z + ad.z));
        exs.w = __expf(lrelu(as.w + ad.w));
        float ws = (hidx == 0) ? exs.x : (hidx == 1) ? exs.y : (hidx == 2) ? exs.z : exs.w;
        float4 hv = g_h4[(size_t)i * 32 + lane];
        den += ws;
        acc.x += ws * hv.x; acc.y += ws * hv.y; acc.z += ws * hv.z; acc.w += ws * hv.w;
    }

    float inv = 1.f / (den + 1e-16f);
    float4 b4 = ((const float4*)bias)[lane];
    float4 o;
    o.x = acc.x * inv + b4.x; o.y = acc.y * inv + b4.y;
    o.z = acc.z * inv + b4.z; o.w = acc.w * inv + b4.w;
    ((float4*)out)[(size_t)i * 32 + lane] = o;
}

// ---------------- launch ----------------
extern "C" void kernel_launch(void* const* d_in, const int* in_sizes, int n_in,
                              void* d_out, int out_size)
{
    const float* x       = (const float*)d_in[0];
    const void*  ei      = d_in[1];
    const float* W       = (const float*)d_in[2];
    const float* att_src = (const float*)d_in[3];
    const float* att_dst = (const float*)d_in[4];
    const float* bias    = (const float*)d_in[5];
    float* out = (float*)d_out;

    int n = in_sizes[0] / 128;
    int E = in_sizes[1] / 2;
    int nb = (n + SCAN_BLK - 1) / SCAN_BLK;
    const int GEMM_SMEM = 128 * 128 * 4;   // 64KB: W only

    cudaFuncSetAttribute(k_gemm, cudaFuncAttributeMaxDynamicSharedMemorySize, GEMM_SMEM);

    k_init<<<(n + 255) / 256, 256>>>(ei, n);
    k_gemm<<<(n + GR - 1) / GR, 256, GEMM_SMEM>>>(x, W, att_src, att_dst, n);
    k_hist<<<(E + 255) / 256, 256>>>(ei, E);
    k_scan1<<<nb, 256>>>(n);
    k_scan2<<<1, 128>>>(nb);
    k_scan3<<<nb, 256>>>(n, E);
    k_fill<<<(E + 255) / 256, 256>>>(ei, E);
    k_gather<<<(n + 7) / 8, 256>>>(bias, out, n);
}

// round 9
// speedup vs baseline: 1.2287x; 1.2287x over previous
#include <cuda_runtime.h>
#include <math.h>

#define NMAX 100000
#define EMAX 1000000

// ---------------- scratch (static device arrays; no allocation) ----------------
__device__ float4 g_h4[(size_t)NMAX * 32];        // h [N,128] as float4
__device__ float4 g_asrc4[NMAX];                  // a_src [N,4]
__device__ float4 g_adst4[NMAX];                  // a_dst [N,4]
__device__ int    g_cnt[NMAX];                    // in-degree counts
__device__ int    g_rowptr[NMAX + 1];             // CSR row pointers (by dst)
__device__ int    g_cur[NMAX];                    // fill cursors
__device__ int    g_part[256];                    // scan block partials
__device__ int    g_adj[EMAX];                    // adjacency: src ids grouped by dst
__device__ int    g_is64;                         // edge_index dtype flag

// ---------------- helpers ----------------
__device__ __forceinline__ int load_idx(const void* ei, long long i, int is64) {
    if (is64) return (int)((const long long*)ei)[i];
    return ((const int*)ei)[i];
}
__device__ __forceinline__ float lrelu(float v) { return v >= 0.f ? v : 0.2f * v; }

#define FMA2(a, xx, ww) asm("fma.rn.f32x2 %0, %1, %2, %0;" : "+l"(a) : "l"(xx), "l"(ww))

// ---------------- init: zero counts + dtype detect ----------------
__global__ void k_init(const void* ei, int n) {
    int i = blockIdx.x * blockDim.x + threadIdx.x;
    if (i < n) g_cnt[i] = 0;
    if (i == 0) {
        const long long* p = (const long long*)ei;
        int ok = 1;
        for (int j = 0; j < 8; j++) {
            long long v = p[j];
            if (v < 0 || v >= n) ok = 0;
        }
        g_is64 = ok;
    }
}

// ---------------- shfl SGEMM: h = x @ W, fused attention dots ----------------
// 256 threads, 8 warps; warp handles 8 rows, lane covers cols lane*4..lane*4+3.
// W (64KB) is the ONLY smem stream (conflict-free per-lane LDS.128); x stays in
// registers, broadcast via shfl (MIO pipe, off the smem crossbar).
#define GR 64
__global__ void __launch_bounds__(256) k_gemm(
    const float* __restrict__ x, const float* __restrict__ W,
    const float* __restrict__ att_src, const float* __restrict__ att_dst, int n)
{
    extern __shared__ float sw[];                 // [128][128] f32 (64KB)
    const int tid = threadIdx.x;
    {
        const float4* W4 = (const float4*)W;
        float4* s4 = (float4*)sw;
        for (int i = tid; i < 128 * 32; i += 256) s4[i] = W4[i];
    }
    __syncthreads();

    const int lane = tid & 31;
    const int wid = tid >> 5;
    const int rowbase = blockIdx.x * GR + wid * 8;
    const unsigned FULL = 0xffffffffu;
    const ulonglong2* swp = (const ulonglong2*)sw;   // k*32 + lane -> 4 cols (16B)
    const float4 as4 = ((const float4*)att_src)[lane];
    const float4 ad4 = ((const float4*)att_dst)[lane];

    float xr[8][4];
#pragma unroll
    for (int r = 0; r < 8; r++) {
        int row = min(rowbase + r, n - 1);
        const float* xp = x + (size_t)row * 128;
#pragma unroll
        for (int j = 0; j < 4; j++) xr[r][j] = xp[j * 32 + lane];
    }

    unsigned long long acc[8][2];
#pragma unroll
    for (int r = 0; r < 8; r++) { acc[r][0] = 0ull; acc[r][1] = 0ull; }

    for (int j = 0; j < 4; j++) {
#pragma unroll
        for (int kk = 0; kk < 32; kk++) {
            ulonglong2 wv = swp[(j * 32 + kk) * 32 + lane];
#pragma unroll
            for (int r = 0; r < 8; r++) {
                float xk = __shfl_sync(FULL, xr[r][j], kk);
                unsigned long long xp2;
                asm("mov.b64 %0, {%1, %1};" : "=l"(xp2) : "f"(xk));
                FMA2(acc[r][0], xp2, wv.x);
                FMA2(acc[r][1], xp2, wv.y);
            }
        }
    }

#pragma unroll
    for (int r = 0; r < 8; r++) {
        int row = rowbase + r;
        if (row < n) {
            float4 h4;
            asm("mov.b64 {%0, %1}, %2;" : "=f"(h4.x), "=f"(h4.y) : "l"(acc[r][0]));
            asm("mov.b64 {%0, %1}, %2;" : "=f"(h4.z), "=f"(h4.w) : "l"(acc[r][1]));
            g_h4[(size_t)row * 32 + lane] = h4;
            float ps = h4.x * as4.x + h4.y * as4.y + h4.z * as4.z + h4.w * as4.w;
            float pd = h4.x * ad4.x + h4.y * ad4.y + h4.z * ad4.z + h4.w * ad4.w;
            ps += __shfl_xor_sync(FULL, ps, 4);
            pd += __shfl_xor_sync(FULL, pd, 4);
            ps += __shfl_xor_sync(FULL, ps, 2);
            pd += __shfl_xor_sync(FULL, pd, 2);
            ps += __shfl_xor_sync(FULL, ps, 1);
            pd += __shfl_xor_sync(FULL, pd, 1);
            if ((lane & 7) == 0) {
                ((float*)g_asrc4)[row * 4 + (lane >> 3)] = ps;
                ((float*)g_adst4)[row * 4 + (lane >> 3)] = pd;
            }
        }
    }
}

// ---------------- CSR build: histogram ----------------
__global__ void k_hist(const void* __restrict__ ei, int E) {
    int e = blockIdx.x * blockDim.x + threadIdx.x;
    if (e >= E) return;
    int dst = load_idx(ei, (long long)E + e, g_is64);
    atomicAdd(&g_cnt[dst], 1);
}

// ---------------- CSR build: scan (3 phases) ----------------
#define SCAN_BLK 1024
__global__ void k_scan1(int n) {
    __shared__ int sred[256];
    int b = blockIdx.x, t = threadIdx.x;
    int base = b * SCAN_BLK + t * 4;
    int s = 0;
#pragma unroll
    for (int u = 0; u < 4; u++) { int idx = base + u; if (idx < n) s += g_cnt[idx]; }
    sred[t] = s; __syncthreads();
    for (int off = 128; off > 0; off >>= 1) {
        if (t < off) sred[t] += sred[t + off];
        __syncthreads();
    }
    if (t == 0) g_part[b] = sred[0];
}
__global__ void k_scan2(int nb) {
    __shared__ int sp[128];
    int t = threadIdx.x;
    int v = (t < nb) ? g_part[t] : 0;
    sp[t] = v; __syncthreads();
    for (int off = 1; off < 128; off <<= 1) {
        int u = (t >= off) ? sp[t - off] : 0;
        __syncthreads();
        sp[t] += u;
        __syncthreads();
    }
    if (t < nb) g_part[t] = sp[t] - v;
}
__global__ void k_scan3(int n, int E) {
    __shared__ int ssum[256];
    int b = blockIdx.x, t = threadIdx.x;
    int base = b * SCAN_BLK + t * 4;
    int c[4]; int s = 0;
#pragma unroll
    for (int u = 0; u < 4; u++) { int idx = base + u; c[u] = (idx < n) ? g_cnt[idx] : 0; s += c[u]; }
    ssum[t] = s; __syncthreads();
    for (int off = 1; off < 256; off <<= 1) {
        int u = (t >= off) ? ssum[t - off] : 0;
        __syncthreads();
        ssum[t] += u;
        __syncthreads();
    }
    int run = g_part[b] + ssum[t] - s;
#pragma unroll
    for (int u = 0; u < 4; u++) {
        int idx = base + u;
        if (idx < n) { g_rowptr[idx] = run; g_cur[idx] = run; run += c[u]; }
    }
    if (b == 0 && t == 0) g_rowptr[n] = E;
}

// ---------------- CSR build: fill ----------------
__global__ void k_fill(const void* __restrict__ ei, int E) {
    int e = blockIdx.x * blockDim.x + threadIdx.x;
    if (e >= E) return;
    int is64 = g_is64;
    int src = load_idx(ei, e, is64);
    int dst = load_idx(ei, (long long)E + e, is64);
    int pos = atomicAdd(&g_cur[dst], 1);
    g_adj[pos] = src;
}

// ---------------- fused gather: inline softmax + aggregation + bias ----------------
// One warp per dst node. Lane l handles output cols 4l..4l+3 (head = l>>3).
// Weights computed inline per-lane: adj via broadcast sequential LDG, the
// head-component of a_src via scalar LDG, exp via MUFU (~1 warp-MUFU/edge,
// far under the MUFU roofline). The h-row loads depend only on adj, so the
// weight chain and the 8-deep h MLP overlap freely. No smem, no syncwarp,
// no warp reductions (every lane sums every edge weight for its head).
// Logits are tiny (|alpha| < ~10) so exp() without max-shift cannot overflow.
__global__ void __launch_bounds__(256) k_gather(
    const float* __restrict__ bias, float* __restrict__ out, int n)
{
    const int lane = threadIdx.x & 31;
    const int i = (blockIdx.x * blockDim.x + threadIdx.x) >> 5;
    if (i >= n) return;
    const int hidx = lane >> 3;
    const float* asrcf = (const float*)g_asrc4;

    int start = g_rowptr[i];
    int deg = g_rowptr[i + 1] - start;
    float adh = ((const float*)g_adst4)[i * 4 + hidx];

    float4 acc = make_float4(0.f, 0.f, 0.f, 0.f);
    float den = 0.f;

    int j = 0;
    for (; j + 8 <= deg; j += 8) {
        int s[8];
#pragma unroll
        for (int u = 0; u < 8; u++) s[u] = g_adj[start + j + u];
        float4 hv[8];
#pragma unroll
        for (int u = 0; u < 8; u++) hv[u] = g_h4[(size_t)s[u] * 32 + lane];
        float w[8];
#pragma unroll
        for (int u = 0; u < 8; u++) {
            float a = asrcf[s[u] * 4 + hidx] + adh;
            w[u] = __expf(lrelu(a));
        }
#pragma unroll
        for (int u = 0; u < 8; u++) {
            den += w[u];
            acc.x += w[u] * hv[u].x; acc.y += w[u] * hv[u].y;
            acc.z += w[u] * hv[u].z; acc.w += w[u] * hv[u].w;
        }
    }
    for (; j < deg; j++) {
        int sj = g_adj[start + j];
        float4 hv = g_h4[(size_t)sj * 32 + lane];
        float a = asrcf[sj * 4 + hidx] + adh;
        float w = __expf(lrelu(a));
        den += w;
        acc.x += w * hv.x; acc.y += w * hv.y; acc.z += w * hv.z; acc.w += w * hv.w;
    }

    // self-loop contribution
    {
        float a = asrcf[i * 4 + hidx] + adh;
        float ws = __expf(lrelu(a));
        float4 hv = g_h4[(size_t)i * 32 + lane];
        den += ws;
        acc.x += ws * hv.x; acc.y += ws * hv.y; acc.z += ws * hv.z; acc.w += ws * hv.w;
    }

    float inv = 1.f / (den + 1e-16f);
    float4 b4 = ((const float4*)bias)[lane];
    float4 o;
    o.x = acc.x * inv + b4.x; o.y = acc.y * inv + b4.y;
    o.z = acc.z * inv + b4.z; o.w = acc.w * inv + b4.w;
    ((float4*)out)[(size_t)i * 32 + lane] = o;
}

// ---------------- launch ----------------
extern "C" void kernel_launch(void* const* d_in, const int* in_sizes, int n_in,
                              void* d_out, int out_size)
{
    const float* x       = (const float*)d_in[0];
    const void*  ei      = d_in[1];
    const float* W       = (const float*)d_in[2];
    const float* att_src = (const float*)d_in[3];
    const float* att_dst = (const float*)d_in[4];
    const float* bias    = (const float*)d_in[5];
    float* out = (float*)d_out;

    int n = in_sizes[0] / 128;
    int E = in_sizes[1] / 2;
    int nb = (n + SCAN_BLK - 1) / SCAN_BLK;
    const int GEMM_SMEM = 128 * 128 * 4;   // 64KB: W only

    cudaFuncSetAttribute(k_gemm, cudaFuncAttributeMaxDynamicSharedMemorySize, GEMM_SMEM);

    k_init<<<(n + 255) / 256, 256>>>(ei, n);
    k_gemm<<<(n + GR - 1) / GR, 256, GEMM_SMEM>>>(x, W, att_src, att_dst, n);
    k_hist<<<(E + 255) / 256, 256>>>(ei, E);
    k_scan1<<<nb, 256>>>(n);
    k_scan2<<<1, 128>>>(nb);
    k_scan3<<<nb, 256>>>(n, E);
    k_fill<<<(E + 255) / 256, 256>>>(ei, E);
    k_gather<<<(n + 7) / 8, 256>>>(bias, out, n);
}

// round 10
// speedup vs baseline: 1.2316x; 1.0024x over previous
#include <cuda_runtime.h>
#include <cuda_fp16.h>
#include <math.h>

#define NMAX 100000
#define EMAX 1000000

// ---------------- scratch (static device arrays; no allocation) ----------------
__device__ __half2 g_h2[(size_t)NMAX * 64];       // h [N,128] as fp16 (half2 pairs)
__device__ float4 g_asrc4[NMAX];                  // a_src [N,4]
__device__ float4 g_adst4[NMAX];                  // a_dst [N,4]
__device__ int    g_cnt[NMAX];                    // in-degree counts
__device__ int    g_rowptr[NMAX + 1];             // CSR row pointers (by dst)
__device__ int    g_cur[NMAX];                    // fill cursors
__device__ int    g_part[256];                    // scan block partials
__device__ int    g_adj[EMAX];                    // adjacency: src ids grouped by dst
__device__ int    g_is64;                         // edge_index dtype flag

// ---------------- helpers ----------------
__device__ __forceinline__ int load_idx(const void* ei, long long i, int is64) {
    if (is64) return (int)((const long long*)ei)[i];
    return ((const int*)ei)[i];
}
__device__ __forceinline__ float lrelu(float v) { return v >= 0.f ? v : 0.2f * v; }

#define FMA2(a, xx, ww) asm("fma.rn.f32x2 %0, %1, %2, %0;" : "+l"(a) : "l"(xx), "l"(ww))

// ---------------- init: zero counts + dtype detect ----------------
__global__ void k_init(const void* ei, int n) {
    int i = blockIdx.x * blockDim.x + threadIdx.x;
    if (i < n) g_cnt[i] = 0;
    if (i == 0) {
        const long long* p = (const long long*)ei;
        int ok = 1;
        for (int j = 0; j < 8; j++) {
            long long v = p[j];
            if (v < 0 || v >= n) ok = 0;
        }
        g_is64 = ok;
    }
}

// ---------------- shfl SGEMM: h = x @ W, fused attention dots ----------------
// 256 threads, 8 warps; warp handles 8 rows, lane covers cols lane*4..lane*4+3.
// W (64KB) is the ONLY smem stream (conflict-free per-lane LDS.128); x stays in
// registers, broadcast via shfl. Attention dots use full fp32 h before the
// fp16 quantization of the stored aggregate operand.
#define GR 64
__global__ void __launch_bounds__(256) k_gemm(
    const float* __restrict__ x, const float* __restrict__ W,
    const float* __restrict__ att_src, const float* __restrict__ att_dst, int n)
{
    extern __shared__ float sw[];                 // [128][128] f32 (64KB)
    const int tid = threadIdx.x;
    {
        const float4* W4 = (const float4*)W;
        float4* s4 = (float4*)sw;
        for (int i = tid; i < 128 * 32; i += 256) s4[i] = W4[i];
    }
    __syncthreads();

    const int lane = tid & 31;
    const int wid = tid >> 5;
    const int rowbase = blockIdx.x * GR + wid * 8;
    const unsigned FULL = 0xffffffffu;
    const ulonglong2* swp = (const ulonglong2*)sw;   // k*32 + lane -> 4 cols (16B)
    const float4 as4 = ((const float4*)att_src)[lane];
    const float4 ad4 = ((const float4*)att_dst)[lane];

    float xr[8][4];
#pragma unroll
    for (int r = 0; r < 8; r++) {
        int row = min(rowbase + r, n - 1);
        const float* xp = x + (size_t)row * 128;
#pragma unroll
        for (int j = 0; j < 4; j++) xr[r][j] = xp[j * 32 + lane];
    }

    unsigned long long acc[8][2];
#pragma unroll
    for (int r = 0; r < 8; r++) { acc[r][0] = 0ull; acc[r][1] = 0ull; }

    for (int j = 0; j < 4; j++) {
#pragma unroll
        for (int kk = 0; kk < 32; kk++) {
            ulonglong2 wv = swp[(j * 32 + kk) * 32 + lane];
#pragma unroll
            for (int r = 0; r < 8; r++) {
                float xk = __shfl_sync(FULL, xr[r][j], kk);
                unsigned long long xp2;
                asm("mov.b64 %0, {%1, %1};" : "=l"(xp2) : "f"(xk));
                FMA2(acc[r][0], xp2, wv.x);
                FMA2(acc[r][1], xp2, wv.y);
            }
        }
    }

#pragma unroll
    for (int r = 0; r < 8; r++) {
        int row = rowbase + r;
        if (row < n) {
            float4 h4;
            asm("mov.b64 {%0, %1}, %2;" : "=f"(h4.x), "=f"(h4.y) : "l"(acc[r][0]));
            asm("mov.b64 {%0, %1}, %2;" : "=f"(h4.z), "=f"(h4.w) : "l"(acc[r][1]));
            // store fp16 aggregate operand (8B per lane)
            __half2 p0 = __floats2half2_rn(h4.x, h4.y);
            __half2 p1 = __floats2half2_rn(h4.z, h4.w);
            uint2 packed;
            packed.x = *(unsigned*)&p0;
            packed.y = *(unsigned*)&p1;
            *(uint2*)&g_h2[(size_t)row * 64 + lane * 2] = packed;
            // attention dots from exact fp32 h
            float ps = h4.x * as4.x + h4.y * as4.y + h4.z * as4.z + h4.w * as4.w;
            float pd = h4.x * ad4.x + h4.y * ad4.y + h4.z * ad4.z + h4.w * ad4.w;
            ps += __shfl_xor_sync(FULL, ps, 4);
            pd += __shfl_xor_sync(FULL, pd, 4);
            ps += __shfl_xor_sync(FULL, ps, 2);
            pd += __shfl_xor_sync(FULL, pd, 2);
            ps += __shfl_xor_sync(FULL, ps, 1);
            pd += __shfl_xor_sync(FULL, pd, 1);
            if ((lane & 7) == 0) {
                ((float*)g_asrc4)[row * 4 + (lane >> 3)] = ps;
                ((float*)g_adst4)[row * 4 + (lane >> 3)] = pd;
            }
        }
    }
}

// ---------------- CSR build: histogram ----------------
__global__ void k_hist(const void* __restrict__ ei, int E) {
    int e = blockIdx.x * blockDim.x + threadIdx.x;
    if (e >= E) return;
    int dst = load_idx(ei, (long long)E + e, g_is64);
    atomicAdd(&g_cnt[dst], 1);
}

// ---------------- CSR build: scan (3 phases) ----------------
#define SCAN_BLK 1024
__global__ void k_scan1(int n) {
    __shared__ int sred[256];
    int b = blockIdx.x, t = threadIdx.x;
    int base = b * SCAN_BLK + t * 4;
    int s = 0;
#pragma unroll
    for (int u = 0; u < 4; u++) { int idx = base + u; if (idx < n) s += g_cnt[idx]; }
    sred[t] = s; __syncthreads();
    for (int off = 128; off > 0; off >>= 1) {
        if (t < off) sred[t] += sred[t + off];
        __syncthreads();
    }
    if (t == 0) g_part[b] = sred[0];
}
__global__ void k_scan2(int nb) {
    __shared__ int sp[128];
    int t = threadIdx.x;
    int v = (t < nb) ? g_part[t] : 0;
    sp[t] = v; __syncthreads();
    for (int off = 1; off < 128; off <<= 1) {
        int u = (t >= off) ? sp[t - off] : 0;
        __syncthreads();
        sp[t] += u;
        __syncthreads();
    }
    if (t < nb) g_part[t] = sp[t] - v;
}
__global__ void k_scan3(int n, int E) {
    __shared__ int ssum[256];
    int b = blockIdx.x, t = threadIdx.x;
    int base = b * SCAN_BLK + t * 4;
    int c[4]; int s = 0;
#pragma unroll
    for (int u = 0; u < 4; u++) { int idx = base + u; c[u] = (idx < n) ? g_cnt[idx] : 0; s += c[u]; }
    ssum[t] = s; __syncthreads();
    for (int off = 1; off < 256; off <<= 1) {
        int u = (t >= off) ? ssum[t - off] : 0;
        __syncthreads();
        ssum[t] += u;
        __syncthreads();
    }
    int run = g_part[b] + ssum[t] - s;
#pragma unroll
    for (int u = 0; u < 4; u++) {
        int idx = base + u;
        if (idx < n) { g_rowptr[idx] = run; g_cur[idx] = run; run += c[u]; }
    }
    if (b == 0 && t == 0) g_rowptr[n] = E;
}

// ---------------- CSR build: fill ----------------
__global__ void k_fill(const void* __restrict__ ei, int E) {
    int e = blockIdx.x * blockDim.x + threadIdx.x;
    if (e >= E) return;
    int is64 = g_is64;
    int src = load_idx(ei, e, is64);
    int dst = load_idx(ei, (long long)E + e, is64);
    int pos = atomicAdd(&g_cur[dst], 1);
    g_adj[pos] = src;
}

// ---------------- fused gather: inline softmax + fp16-h aggregation + bias ----------------
// One warp per dst node. Lane l handles output cols 4l..4l+3 (head = l>>3).
// h rows read as fp16 (8B per lane, 256B per warp) -> half the R9 traffic.
// Weights computed inline per-lane; denominator is a free running sum.
// Logits are tiny (|alpha| < ~10) so exp() without max-shift cannot overflow.
__global__ void __launch_bounds__(256) k_gather(
    const float* __restrict__ bias, float* __restrict__ out, int n)
{
    const int lane = threadIdx.x & 31;
    const int i = (blockIdx.x * blockDim.x + threadIdx.x) >> 5;
    if (i >= n) return;
    const int hidx = lane >> 3;
    const float* asrcf = (const float*)g_asrc4;

    int start = g_rowptr[i];
    int deg = g_rowptr[i + 1] - start;
    float adh = ((const float*)g_adst4)[i * 4 + hidx];

    float4 acc = make_float4(0.f, 0.f, 0.f, 0.f);
    float den = 0.f;

    int j = 0;
    for (; j + 8 <= deg; j += 8) {
        int s[8];
#pragma unroll
        for (int u = 0; u < 8; u++) s[u] = g_adj[start + j + u];
        uint2 hb[8];
#pragma unroll
        for (int u = 0; u < 8; u++) hb[u] = *(const uint2*)&g_h2[(size_t)s[u] * 64 + lane * 2];
        float w[8];
#pragma unroll
        for (int u = 0; u < 8; u++) {
            float a = asrcf[s[u] * 4 + hidx] + adh;
            w[u] = __expf(lrelu(a));
        }
#pragma unroll
        for (int u = 0; u < 8; u++) {
            float2 lo = __half22float2(*(const __half2*)&hb[u].x);
            float2 hi = __half22float2(*(const __half2*)&hb[u].y);
            den += w[u];
            acc.x += w[u] * lo.x; acc.y += w[u] * lo.y;
            acc.z += w[u] * hi.x; acc.w += w[u] * hi.y;
        }
    }
    for (; j < deg; j++) {
        int sj = g_adj[start + j];
        uint2 hb = *(const uint2*)&g_h2[(size_t)sj * 64 + lane * 2];
        float a = asrcf[sj * 4 + hidx] + adh;
        float w = __expf(lrelu(a));
        float2 lo = __half22float2(*(const __half2*)&hb.x);
        float2 hi = __half22float2(*(const __half2*)&hb.y);
        den += w;
        acc.x += w * lo.x; acc.y += w * lo.y;
        acc.z += w * hi.x; acc.w += w * hi.y;
    }

    // self-loop contribution
    {
        float a = asrcf[i * 4 + hidx] + adh;
        float ws = __expf(lrelu(a));
        uint2 hb = *(const uint2*)&g_h2[(size_t)i * 64 + lane * 2];
        float2 lo = __half22float2(*(const __half2*)&hb.x);
        float2 hi = __half22float2(*(const __half2*)&hb.y);
        den += ws;
        acc.x += ws * lo.x; acc.y += ws * lo.y;
        acc.z += ws * hi.x; acc.w += ws * hi.y;
    }

    float inv = 1.f / (den + 1e-16f);
    float4 b4 = ((const float4*)bias)[lane];
    float4 o;
    o.x = acc.x * inv + b4.x; o.y = acc.y * inv + b4.y;
    o.z = acc.z * inv + b4.z; o.w = acc.w * inv + b4.w;
    ((float4*)out)[(size_t)i * 32 + lane] = o;
}

// ---------------- launch ----------------
extern "C" void kernel_launch(void* const* d_in, const int* in_sizes, int n_in,
                              void* d_out, int out_size)
{
    const float* x       = (const float*)d_in[0];
    const void*  ei      = d_in[1];
    const float* W       = (const float*)d_in[2];
    const float* att_src = (const float*)d_in[3];
    const float* att_dst = (const float*)d_in[4];
    const float* bias    = (const float*)d_in[5];
    float* out = (float*)d_out;

    int n = in_sizes[0] / 128;
    int E = in_sizes[1] / 2;
    int nb = (n + SCAN_BLK - 1) / SCAN_BLK;
    const int GEMM_SMEM = 128 * 128 * 4;   // 64KB: W only

    cudaFuncSetAttribute(k_gemm, cudaFuncAttributeMaxDynamicSharedMemorySize, GEMM_SMEM);

    k_init<<<(n + 255) / 256, 256>>>(ei, n);
    k_gemm<<<(n + GR - 1) / GR, 256, GEMM_SMEM>>>(x, W, att_src, att_dst, n);
    k_hist<<<(E + 255) / 256, 256>>>(ei, E);
    k_scan1<<<nb, 256>>>(n);
    k_scan2<<<1, 128>>>(nb);
    k_scan3<<<nb, 256>>>(n, E);
    k_fill<<<(E + 255) / 256, 256>>>(ei, E);
    k_gather<<<(n + 7) / 8, 256>>>(bias, out, n);
}

// round 11
// speedup vs baseline: 1.5350x; 1.2463x over previous
#include <cuda_runtime.h>
#include <cuda_fp16.h>
#include <math.h>

#define NMAX 100000
#define EMAX 1000000

// ---------------- scratch (static device arrays; no allocation) ----------------
__device__ float4 g_h4[(size_t)NMAX * 32];        // h [N,128] fp32 as float4
__device__ float4 g_asrc4[NMAX];                  // a_src [N,4]
__device__ float4 g_adst4[NMAX];                  // a_dst [N,4]
__device__ int    g_cnt[NMAX];                    // in-degree counts
__device__ int    g_rowptr[NMAX + 1];             // CSR row pointers (by dst)
__device__ int    g_cur[NMAX];                    // fill cursors
__device__ int    g_part[256];                    // scan block partials
__device__ int    g_adj[EMAX];                    // adjacency: src ids grouped by dst
__device__ int    g_is64;                         // edge_index dtype flag

// ---------------- helpers ----------------
__device__ __forceinline__ int load_idx(const void* ei, long long i, int is64) {
    if (is64) return (int)((const long long*)ei)[i];
    return ((const int*)ei)[i];
}
__device__ __forceinline__ float lrelu(float v) { return v >= 0.f ? v : 0.2f * v; }

// ---------------- init: zero counts + dtype detect ----------------
__global__ void k_init(const void* ei, int n) {
    int i = blockIdx.x * blockDim.x + threadIdx.x;
    if (i < n) g_cnt[i] = 0;
    if (i == 0) {
        const long long* p = (const long long*)ei;
        int ok = 1;
        for (int j = 0; j < 8; j++) {
            long long v = p[j];
            if (v < 0 || v >= n) ok = 0;
        }
        g_is64 = ok;
    }
}

// ---------------- HMMA GEMM: h = x @ W (fp16 inputs, fp32 accum) ----------------
// Block: 256 thr = 8 warps covering M=64 rows x N=128 cols.
// Warp (wr 0-1, wc 0-3): rows [wr*32, +32), cols [wc*32, +32).
// Per warp: 2 m-tiles x 4 n-tiles of m16n8k16, K = 8 k-tiles.
// Fragments loaded with plain LDS.32 per the PTX fragment spec (no ldmatrix):
//   A: a0=A[g][2t+{0,1}] a1=A[g+8][..] a2=A[g][2t+8+{0,1}] a3=A[g+8][+8]
//   B: b0=B[2t+{0,1}][nc] b1=B[2t+8+{0,1}][nc]   (W staged TRANSPOSED: swt[n][k])
//   C: c0,c1=row g, col 2t+{0,1}; c2,c3=row g+8.
// smem stride 136 halves: all u32 loads 4B-aligned, fragment LDS conflict-free
// (row step -> 4-bank step; 8 groups x 4 lanes cover all 32 banks).
#define GR 64
#define GSTR 136
#define GEMM_SMEM ((64 + 128) * GSTR * 2)

#define MMA16816(C, A0, A1, A2, A3, B0, B1) \
    asm volatile("mma.sync.aligned.m16n8k16.row.col.f32.f16.f16.f32 " \
                 "{%0,%1,%2,%3}, {%4,%5,%6,%7}, {%8,%9}, {%0,%1,%2,%3};" \
                 : "+f"((C)[0]), "+f"((C)[1]), "+f"((C)[2]), "+f"((C)[3]) \
                 : "r"(A0), "r"(A1), "r"(A2), "r"(A3), "r"(B0), "r"(B1))

__global__ void __launch_bounds__(256) k_gemm(
    const float* __restrict__ x, const float* __restrict__ W, int n)
{
    extern __shared__ __half sh[];
    __half* sxh = sh;                    // [64][GSTR] x tile (row-major, fp16)
    __half* swt = sh + 64 * GSTR;        // [128][GSTR] W transposed: swt[n][k]
    const int tid = threadIdx.x;
    const int rowbase = blockIdx.x * GR;

    // stage x tile (coalesced read, conflict-free 2B smem stores)
    for (int i = tid; i < 64 * 128; i += 256) {
        int r = i >> 7, c = i & 127;
        int gr = min(rowbase + r, n - 1);
        sxh[r * GSTR + c] = __float2half(x[(size_t)gr * 128 + c]);
    }
    // stage W transposed (coalesced read W[k][c]; ~4-phase smem store, one-time)
    for (int i = tid; i < 128 * 128; i += 256) {
        int k = i >> 7, c = i & 127;
        swt[c * GSTR + k] = __float2half(W[i]);
    }
    __syncthreads();

    const int lane = tid & 31;
    const int wid = tid >> 5;
    const int wr = wid >> 2, wc = wid & 3;
    const int grp = lane >> 2, thr = lane & 3;

    float acc[2][4][4];
#pragma unroll
    for (int mt = 0; mt < 2; mt++)
#pragma unroll
        for (int nt = 0; nt < 4; nt++)
#pragma unroll
            for (int q = 0; q < 4; q++) acc[mt][nt][q] = 0.f;

#pragma unroll
    for (int kt = 0; kt < 8; kt++) {
        unsigned b[4][2];
#pragma unroll
        for (int nt = 0; nt < 4; nt++) {
            int ncol = wc * 32 + nt * 8 + grp;
            const __half* bp = &swt[ncol * GSTR + kt * 16 + 2 * thr];
            b[nt][0] = *(const unsigned*)bp;
            b[nt][1] = *(const unsigned*)(bp + 8);
        }
#pragma unroll
        for (int mt = 0; mt < 2; mt++) {
            int r0 = wr * 32 + mt * 16 + grp;
            const __half* ap0 = &sxh[r0 * GSTR + kt * 16 + 2 * thr];
            const __half* ap1 = ap0 + 8 * GSTR;
            unsigned a0 = *(const unsigned*)ap0;
            unsigned a1 = *(const unsigned*)ap1;
            unsigned a2 = *(const unsigned*)(ap0 + 8);
            unsigned a3 = *(const unsigned*)(ap1 + 8);
#pragma unroll
            for (int nt = 0; nt < 4; nt++)
                MMA16816(acc[mt][nt], a0, a1, a2, a3, b[nt][0], b[nt][1]);
        }
    }

    // epilogue: fp32 h store (float2 per fragment pair, 8B aligned: col even)
    float* gh = (float*)g_h4;
#pragma unroll
    for (int mt = 0; mt < 2; mt++) {
        int r0 = rowbase + wr * 32 + mt * 16 + grp;
        int r1 = r0 + 8;
#pragma unroll
        for (int nt = 0; nt < 4; nt++) {
            int c = wc * 32 + nt * 8 + 2 * thr;
            if (r0 < n)
                *(float2*)&gh[(size_t)r0 * 128 + c] = make_float2(acc[mt][nt][0], acc[mt][nt][1]);
            if (r1 < n)
                *(float2*)&gh[(size_t)r1 * 128 + c] = make_float2(acc[mt][nt][2], acc[mt][nt][3]);
        }
    }
}

// ---------------- attention dots: a_src/a_dst from h ----------------
__global__ void __launch_bounds__(256) k_att(
    const float* __restrict__ att_src, const float* __restrict__ att_dst, int n)
{
    const int lane = threadIdx.x & 31;
    const int i = (blockIdx.x * blockDim.x + threadIdx.x) >> 5;
    if (i >= n) return;
    float4 as4 = ((const float4*)att_src)[lane];
    float4 ad4 = ((const float4*)att_dst)[lane];
    float4 h4 = g_h4[(size_t)i * 32 + lane];
    float ps = h4.x * as4.x + h4.y * as4.y + h4.z * as4.z + h4.w * as4.w;
    float pd = h4.x * ad4.x + h4.y * ad4.y + h4.z * ad4.z + h4.w * ad4.w;
    const unsigned FULL = 0xffffffffu;
    ps += __shfl_xor_sync(FULL, ps, 4);
    pd += __shfl_xor_sync(FULL, pd, 4);
    ps += __shfl_xor_sync(FULL, ps, 2);
    pd += __shfl_xor_sync(FULL, pd, 2);
    ps += __shfl_xor_sync(FULL, ps, 1);
    pd += __shfl_xor_sync(FULL, pd, 1);
    if ((lane & 7) == 0) {
        ((float*)g_asrc4)[i * 4 + (lane >> 3)] = ps;
        ((float*)g_adst4)[i * 4 + (lane >> 3)] = pd;
    }
}

// ---------------- CSR build: histogram ----------------
__global__ void k_hist(const void* __restrict__ ei, int E) {
    int e = blockIdx.x * blockDim.x + threadIdx.x;
    if (e >= E) return;
    int dst = load_idx(ei, (long long)E + e, g_is64);
    atomicAdd(&g_cnt[dst], 1);
}

// ---------------- CSR build: scan (2 kernels; partial-prefix inlined) ----------------
#define SCAN_BLK 1024
__global__ void k_scan1(int n) {
    __shared__ int sred[256];
    int b = blockIdx.x, t = threadIdx.x;
    int base = b * SCAN_BLK + t * 4;
    int s = 0;
#pragma unroll
    for (int u = 0; u < 4; u++) { int idx = base + u; if (idx < n) s += g_cnt[idx]; }
    sred[t] = s; __syncthreads();
    for (int off = 128; off > 0; off >>= 1) {
        if (t < off) sred[t] += sred[t + off];
        __syncthreads();
    }
    if (t == 0) g_part[b] = sred[0];
}
__global__ void k_scan3(int n, int E, int nb) {
    __shared__ int ssum[256];
    __shared__ int spre[128];
    int b = blockIdx.x, t = threadIdx.x;
    // prefix of partials < b (nb <= 128)
    if (t < 128) spre[t] = (t < nb && t < b) ? g_part[t] : 0;
    __syncthreads();
    if (t < 64) spre[t] += spre[t + 64];
    __syncthreads();
    if (t < 32) spre[t] += spre[t + 32];
    __syncthreads();
    if (t < 16) spre[t] += spre[t + 16];
    __syncthreads();
    if (t < 8) spre[t] += spre[t + 8];
    __syncthreads();
    if (t < 4) spre[t] += spre[t + 4];
    __syncthreads();
    if (t < 2) spre[t] += spre[t + 2];
    __syncthreads();
    if (t < 1) spre[t] += spre[t + 1];
    __syncthreads();
    int prefix = spre[0];

    int base = b * SCAN_BLK + t * 4;
    int c[4]; int s = 0;
#pragma unroll
    for (int u = 0; u < 4; u++) { int idx = base + u; c[u] = (idx < n) ? g_cnt[idx] : 0; s += c[u]; }
    ssum[t] = s; __syncthreads();
    for (int off = 1; off < 256; off <<= 1) {
        int u = (t >= off) ? ssum[t - off] : 0;
        __syncthreads();
        ssum[t] += u;
        __syncthreads();
    }
    int run = prefix + ssum[t] - s;
#pragma unroll
    for (int u = 0; u < 4; u++) {
        int idx = base + u;
        if (idx < n) { g_rowptr[idx] = run; g_cur[idx] = run; run += c[u]; }
    }
    if (b == 0 && t == 0) g_rowptr[n] = E;
}

// ---------------- CSR build: fill ----------------
__global__ void k_fill(const void* __restrict__ ei, int E) {
    int e = blockIdx.x * blockDim.x + threadIdx.x;
    if (e >= E) return;
    int is64 = g_is64;
    int src = load_idx(ei, e, is64);
    int dst = load_idx(ei, (long long)E + e, is64);
    int pos = atomicAdd(&g_cur[dst], 1);
    g_adj[pos] = src;
}

// ---------------- fused gather: inline softmax + aggregation + bias ----------------
// (R9 proven version, fp32 h.) One warp per dst node; lane l covers cols
// 4l..4l+3 (head = l>>3). Weights computed inline per-lane; denominator is a
// free running sum. No smem, no syncwarp, no warp reductions.
__global__ void __launch_bounds__(256) k_gather(
    const float* __restrict__ bias, float* __restrict__ out, int n)
{
    const int lane = threadIdx.x & 31;
    const int i = (blockIdx.x * blockDim.x + threadIdx.x) >> 5;
    if (i >= n) return;
    const int hidx = lane >> 3;
    const float* asrcf = (const float*)g_asrc4;

    int start = g_rowptr[i];
    int deg = g_rowptr[i + 1] - start;
    float adh = ((const float*)g_adst4)[i * 4 + hidx];

    float4 acc = make_float4(0.f, 0.f, 0.f, 0.f);
    float den = 0.f;

    int j = 0;
    for (; j + 8 <= deg; j += 8) {
        int s[8];
#pragma unroll
        for (int u = 0; u < 8; u++) s[u] = g_adj[start + j + u];
        float4 hv[8];
#pragma unroll
        for (int u = 0; u < 8; u++) hv[u] = g_h4[(size_t)s[u] * 32 + lane];
        float w[8];
#pragma unroll
        for (int u = 0; u < 8; u++) {
            float a = asrcf[s[u] * 4 + hidx] + adh;
            w[u] = __expf(lrelu(a));
        }
#pragma unroll
        for (int u = 0; u < 8; u++) {
            den += w[u];
            acc.x += w[u] * hv[u].x; acc.y += w[u] * hv[u].y;
            acc.z += w[u] * hv[u].z; acc.w += w[u] * hv[u].w;
        }
    }
    for (; j < deg; j++) {
        int sj = g_adj[start + j];
        float4 hv = g_h4[(size_t)sj * 32 + lane];
        float a = asrcf[sj * 4 + hidx] + adh;
        float w = __expf(lrelu(a));
        den += w;
        acc.x += w * hv.x; acc.y += w * hv.y; acc.z += w * hv.z; acc.w += w * hv.w;
    }

    // self-loop contribution
    {
        float a = asrcf[i * 4 + hidx] + adh;
        float ws = __expf(lrelu(a));
        float4 hv = g_h4[(size_t)i * 32 + lane];
        den += ws;
        acc.x += ws * hv.x; acc.y += ws * hv.y; acc.z += ws * hv.z; acc.w += ws * hv.w;
    }

    float inv = 1.f / (den + 1e-16f);
    float4 b4 = ((const float4*)bias)[lane];
    float4 o;
    o.x = acc.x * inv + b4.x; o.y = acc.y * inv + b4.y;
    o.z = acc.z * inv + b4.z; o.w = acc.w * inv + b4.w;
    ((float4*)out)[(size_t)i * 32 + lane] = o;
}

// ---------------- launch ----------------
extern "C" void kernel_launch(void* const* d_in, const int* in_sizes, int n_in,
                              void* d_out, int out_size)
{
    const float* x       = (const float*)d_in[0];
    const void*  ei      = d_in[1];
    const float* W       = (const float*)d_in[2];
    const float* att_src = (const float*)d_in[3];
    const float* att_dst = (const float*)d_in[4];
    const float* bias    = (const float*)d_in[5];
    float* out = (float*)d_out;

    int n = in_sizes[0] / 128;
    int E = in_sizes[1] / 2;
    int nb = (n + SCAN_BLK - 1) / SCAN_BLK;

    cudaFuncSetAttribute(k_gemm, cudaFuncAttributeMaxDynamicSharedMemorySize, GEMM_SMEM);

    k_init<<<(n + 255) / 256, 256>>>(ei, n);
    k_gemm<<<(n + GR - 1) / GR, 256, GEMM_SMEM>>>(x, W, n);
    k_att<<<(n * 32 + 255) / 256, 256>>>(att_src, att_dst, n);
    k_hist<<<(E + 255) / 256, 256>>>(ei, E);
    k_scan1<<<nb, 256>>>(n);
    k_scan3<<<nb, 256>>>(n, E, nb);
    k_fill<<<(E + 255) / 256, 256>>>(ei, E);
    k_gather<<<(n + 7) / 8, 256>>>(bias, out, n);
}